// round 6
// baseline (speedup 1.0000x reference)
#include <cuda_runtime.h>
#include <math.h>

typedef unsigned long long ull;

#define Bb 32
#define Tt 8
#define Nn 150
#define Ff 16
#define Hh 32
#define Rr 4
#define Ee 16
#define NT 10
#define NTILES 15

#define BNH  (Bb*Nn*Hh)
#define OUTE (Bb*Tt*Nn*Hh*Rr)

// ---------------- device state ----------------
__device__ float4 g_AfP[Nn*Nn];          // table: (s.x, s.w, s.y, s.y)
__device__ float2 g_AfB[Nn*Nn];          // table: (-s.z, s.z)
__device__ float  g_adj[Nn*Nn*Rr];
__device__ float4 g_WP[10][Hh*Hh];       // weight tables, same packing
__device__ float2 g_WB[10][Hh*Hh];
__device__ float4 g_Xf[Tt*Bb*Nn*Ff];     // variable layout: (S0, S2, Re, Im)
__device__ float4 g_hf[2][2][BNH];       // spectral hidden (variable layout) [layer][buf]
__device__ float4 g_ht[2][2][BNH];       // time-domain hidden
__device__ float4 g_z4[BNH];             // zeros (works for both layouts)
__device__ float4 g_Zg[2][BNH];
__device__ float4 g_RH[2][BNH];          // fft(R*H) variable layout
__device__ float4 g_Gf[2][BNH];          // candidate stash (pair layout d0,d1)

// ---------------- packed f32x2 helpers ----------------
__device__ __forceinline__ void ffma2(ull& d, ull a, ull b) {
    asm("fma.rn.f32x2 %0, %1, %2, %0;" : "+l"(d) : "l"(a), "l"(b));
}
__device__ __forceinline__ ull fadd2(ull a, ull b) {
    ull r; asm("add.rn.f32x2 %0, %1, %2;" : "=l"(r) : "l"(a), "l"(b)); return r;
}
__device__ __forceinline__ float2 u2f(ull v) {
    float2 r; asm("mov.b64 {%0, %1}, %2;" : "=f"(r.x), "=f"(r.y) : "l"(v)); return r;
}
__device__ __forceinline__ ull f2u(float a, float b) {
    ull v; asm("mov.b64 %0, {%1, %2};" : "=l"(v) : "f"(a), "f"(b)); return v;
}
__device__ __forceinline__ ull swap2(ull v) {
    float2 t = u2f(v); return f2u(t.y, t.x);
}

// ---------------- FFT helpers (jnp convention, R=4) ----------------
__device__ __forceinline__ float4 fft4(float x0, float x1, float x2, float x3) {
    return make_float4(x0 + x1 + x2 + x3, x0 - x2, x3 - x1, x0 - x1 + x2 - x3);
}
// spectral -> time from pair accumulators d0=(S0,S2), d1=(Re,Im)
__device__ __forceinline__ void ifft4p(ull d0, ull d1, float* x) {
    float2 a = u2f(d0), b = u2f(d1);
    x[0] = 0.25f * (a.x + 2.f * b.x + a.y);
    x[1] = 0.25f * (a.x - 2.f * b.y - a.y);
    x[2] = 0.25f * (a.x - 2.f * b.x + a.y);
    x[3] = 0.25f * (a.x + 2.f * b.y - a.y);
}
__device__ __forceinline__ float sigm(float v) { return 1.f / (1.f + expf(-v)); }

// ---------------- precompute ----------------
__global__ void k_init() {
    int i = blockIdx.x * blockDim.x + threadIdx.x;
    if (i < BNH) g_z4[i] = make_float4(0.f, 0.f, 0.f, 0.f);
}

__global__ void k_adj_raw(const float* __restrict__ U) {
    int idx = blockIdx.x * blockDim.x + threadIdx.x;
    if (idx >= Nn * Nn) return;
    int n = idx / Nn, m = idx % Nn;
    float4 g = make_float4(0.f, 0.f, 0.f, 0.f);
    for (int e = 0; e < Ee; e++) {
        const float* un = U + (n * Ee + e) * Rr;
        const float* um = U + (m * Ee + e) * Rr;
        float4 a = fft4(un[0], un[1], un[2], un[3]);
        float4 b = fft4(um[0], um[1], um[2], um[3]);
        g.x += a.x * b.x;
        g.y += a.y * b.y - a.z * b.z;
        g.z += a.y * b.z + a.z * b.y;
        g.w += a.w * b.w;
    }
    float x0 = 0.25f * (g.x + 2.f * g.y + g.w);
    float x1 = 0.25f * (g.x - 2.f * g.z - g.w);
    float x2 = 0.25f * (g.x - 2.f * g.y + g.w);
    float x3 = 0.25f * (g.x + 2.f * g.z - g.w);
    g_adj[idx * 4 + 0] = fmaxf(x0, 0.f);
    g_adj[idx * 4 + 1] = fmaxf(x1, 0.f);
    g_adj[idx * 4 + 2] = fmaxf(x2, 0.f);
    g_adj[idx * 4 + 3] = fmaxf(x3, 0.f);
}

__global__ void k_softmax() {
    int n = blockIdx.x, r = blockIdx.y;
    int tid = threadIdx.x;
    __shared__ float red[256];
    float v = (tid < Nn) ? g_adj[(n * Nn + tid) * Rr + r] : -1e30f;
    red[tid] = v;
    __syncthreads();
    for (int s = 128; s > 0; s >>= 1) {
        if (tid < s) red[tid] = fmaxf(red[tid], red[tid + s]);
        __syncthreads();
    }
    float mx = red[0];
    __syncthreads();
    float e = (tid < Nn) ? expf(v - mx) : 0.f;
    red[tid] = e;
    __syncthreads();
    for (int s = 128; s > 0; s >>= 1) {
        if (tid < s) red[tid] += red[tid + s];
        __syncthreads();
    }
    float inv = 1.f / red[0];
    if (tid < Nn) g_adj[(n * Nn + tid) * Rr + r] = e * inv;
}

__global__ void k_adj_fft() {
    int idx = blockIdx.x * blockDim.x + threadIdx.x;
    if (idx >= Nn * Nn) return;
    const float* a = g_adj + idx * 4;
    float4 s = fft4(a[0], a[1], a[2], a[3]);
    g_AfP[idx] = make_float4(s.x, s.w, s.y, s.y);
    g_AfB[idx] = make_float2(-s.z, s.z);
}

__global__ void k_wfft_all(const float* p0, const float* p1, const float* p2,
                           const float* p3, const float* p4, const float* p5,
                           const float* p6, const float* p7, const float* p8,
                           const float* p9) {
    int idx = blockIdx.x * blockDim.x + threadIdx.x;
    const int small = Ff * Hh, big = Hh * Hh;
    if (idx >= 3 * small + 7 * big) return;
    int wi, off;
    if (idx < 3 * small) { wi = idx / small; off = idx % small; }
    else { int j = idx - 3 * small; wi = 3 + j / big; off = j % big; }
    const float* ps[10] = {p0, p1, p2, p3, p4, p5, p6, p7, p8, p9};
    const float* w = ps[wi] + off * Rr;
    float4 s = fft4(w[0], w[1], w[2], w[3]);
    g_WP[wi][off] = make_float4(s.x, s.w, s.y, s.y);
    g_WB[wi][off] = make_float2(-s.z, s.z);
}

__global__ void k_xfft(const float* __restrict__ inputs) {
    int idx = blockIdx.x * blockDim.x + threadIdx.x;
    if (idx >= Tt * Bb * Nn * Ff) return;
    int f = idx % Ff;
    int n = (idx / Ff) % Nn;
    int b = (idx / (Ff * Nn)) % Bb;
    int t = idx / (Ff * Nn * Bb);
    const float* p = inputs + ((((size_t)b * Tt + t) * Nn + n) * Ff + f) * Rr;
    float4 s = fft4(p[0], p[1], p[2], p[3]);
    g_Xf[idx] = make_float4(s.x, s.w, s.y, s.z);
}

// ---------------- shared tile loader ----------------
__device__ __forceinline__ void load_tiles(int tid, int n0,
        ulonglong2* s_AfP, ulonglong2* s_AfB2) {
    const ulonglong2* AfP = (const ulonglong2*)g_AfP;
    for (int i = tid; i < NT * Nn; i += 64) {
        int j = i / Nn, m = i % Nn;
        s_AfP[i] = AfP[(n0 + j) * Nn + m];
    }
    for (int i = tid; i < Nn * (NT / 2); i += 64) {
        int m = i / (NT / 2), jp = i % (NT / 2);
        float2 b0 = g_AfB[(n0 + 2 * jp) * Nn + m];
        float2 b1 = g_AfB[(n0 + 2 * jp + 1) * Nn + m];
        s_AfB2[i] = make_ulonglong2(f2u(b0.x, b0.y), f2u(b1.x, b1.y));
    }
}

// agg inner: one channel, accumulate rows n0..n0+9 over m range
__device__ __forceinline__ void agg_m(const float4* in, int stride, int m0, int m1,
        const ulonglong2* s_AfP, const ulonglong2* s_AfB2, ull* d0, ull* d1) {
    for (int m = m0; m < m1; m++) {
        float4 v = in[(size_t)m * stride];
        ull q0 = f2u(v.x, v.y), q1 = f2u(v.z, v.w), q2 = f2u(v.w, v.z);
        #pragma unroll
        for (int jp = 0; jp < NT / 2; jp++) {
            ulonglong2 pb = s_AfB2[m * (NT / 2) + jp];
            ulonglong2 p = s_AfP[(2 * jp) * Nn + m];
            ffma2(d0[2 * jp], p.x, q0);
            ffma2(d1[2 * jp], p.y, q1);
            ffma2(d1[2 * jp], pb.x, q2);
            p = s_AfP[(2 * jp + 1) * Nn + m];
            ffma2(d0[2 * jp + 1], p.x, q0);
            ffma2(d1[2 * jp + 1], p.y, q1);
            ffma2(d1[2 * jp + 1], pb.y, q2);
        }
    }
}

// ---------------- stage kernels ----------------
struct S1 {
    const float4 *Xf, *Hf, *hs;
    const float4 *WzP, *WrP, *WhP, *UzP, *UrP;
    const float2 *WzB, *WrB, *WhB, *UzB, *UrB;
    const float4 *bias;
    float4 *Z, *RHf, *Gf;
    int Fin;
};

__global__ void __launch_bounds__(64) k_stage1(S1 A0, S1 A1) {
    __shared__ ulonglong2 s_AfP[NT * Nn];
    __shared__ ulonglong2 s_AfB2[Nn * (NT / 2)];
    __shared__ ull s_q0[NT * 64], s_q1[NT * 64];
    const S1 a = blockIdx.z ? A1 : A0;
    const int tid = threadIdx.x, b = blockIdx.y, n0 = blockIdx.x * NT;
    load_tiles(tid, n0, s_AfP, s_AfB2);
    __syncthreads();

    const int C = a.Fin + Hh;
    if (tid < C) {
        const float4* in;
        int stride;
        if (tid < a.Fin) { in = a.Xf + (size_t)b * Nn * a.Fin + tid; stride = a.Fin; }
        else             { in = a.Hf + (size_t)b * Nn * Hh + (tid - a.Fin); stride = Hh; }
        ull d0[NT], d1[NT];
        #pragma unroll
        for (int j = 0; j < NT; j++) { d0[j] = 0; d1[j] = 0; }
        agg_m(in, stride, 0, Nn, s_AfP, s_AfB2, d0, d1);
        #pragma unroll
        for (int j = 0; j < NT; j++) { s_q0[j * C + tid] = d0[j]; s_q1[j * C + tid] = d1[j]; }
    }
    __syncthreads();

    const int h = tid & 31, g = tid >> 5;
    ull z0[5], z1[5], r0[5], r1[5], c0[5], c1[5];
    #pragma unroll
    for (int k = 0; k < 5; k++) { z0[k]=0; z1[k]=0; r0[k]=0; r1[k]=0; c0[k]=0; c1[k]=0; }

    const ulonglong2* WzP = (const ulonglong2*)a.WzP;
    const ulonglong2* WrP = (const ulonglong2*)a.WrP;
    const ulonglong2* WhP = (const ulonglong2*)a.WhP;
    for (int f = 0; f < a.Fin; f++) {
        int wi = f * Hh + h;
        ulonglong2 wz = WzP[wi]; ull wzb = f2u(a.WzB[wi].x, a.WzB[wi].y);
        ulonglong2 wr = WrP[wi]; ull wrb = f2u(a.WrB[wi].x, a.WrB[wi].y);
        ulonglong2 wh = WhP[wi]; ull whb = f2u(a.WhB[wi].x, a.WhB[wi].y);
        #pragma unroll
        for (int k = 0; k < 5; k++) {
            int i = (g * 5 + k) * C + f;
            ull q0 = s_q0[i], q1 = s_q1[i], q2 = swap2(q1);
            ffma2(z0[k], wz.x, q0); ffma2(z1[k], wz.y, q1); ffma2(z1[k], wzb, q2);
            ffma2(r0[k], wr.x, q0); ffma2(r1[k], wr.y, q1); ffma2(r1[k], wrb, q2);
            ffma2(c0[k], wh.x, q0); ffma2(c1[k], wh.y, q1); ffma2(c1[k], whb, q2);
        }
    }
    const ulonglong2* UzP = (const ulonglong2*)a.UzP;
    const ulonglong2* UrP = (const ulonglong2*)a.UrP;
    for (int j = 0; j < Hh; j++) {
        int wi = j * Hh + h;
        ulonglong2 uz = UzP[wi]; ull uzb = f2u(a.UzB[wi].x, a.UzB[wi].y);
        ulonglong2 ur = UrP[wi]; ull urb = f2u(a.UrB[wi].x, a.UrB[wi].y);
        #pragma unroll
        for (int k = 0; k < 5; k++) {
            int i = (g * 5 + k) * C + a.Fin + j;
            ull q0 = s_q0[i], q1 = s_q1[i], q2 = swap2(q1);
            ffma2(z0[k], uz.x, q0); ffma2(z1[k], uz.y, q1); ffma2(z1[k], uzb, q2);
            ffma2(r0[k], ur.x, q0); ffma2(r1[k], ur.y, q1); ffma2(r1[k], urb, q2);
        }
    }

    const float4 bz = a.bias[h], br = a.bias[Hh + h];
    #pragma unroll
    for (int k = 0; k < 5; k++) {
        int idx = (b * Nn + n0 + g * 5 + k) * Hh + h;
        float zt[4], rt[4];
        ifft4p(z0[k], z1[k], zt);
        ifft4p(r0[k], r1[k], rt);
        float4 hv = a.hs[idx];
        a.Z[idx] = make_float4(sigm(zt[0] + bz.x), sigm(zt[1] + bz.y),
                               sigm(zt[2] + bz.z), sigm(zt[3] + bz.w));
        float rh0 = sigm(rt[0] + br.x) * hv.x;
        float rh1 = sigm(rt[1] + br.y) * hv.y;
        float rh2 = sigm(rt[2] + br.z) * hv.z;
        float rh3 = sigm(rt[3] + br.w) * hv.w;
        float4 s = fft4(rh0, rh1, rh2, rh3);
        a.RHf[idx] = make_float4(s.x, s.w, s.y, s.z);
        *(ulonglong2*)&a.Gf[idx] = make_ulonglong2(c0[k], c1[k]);
    }
}

struct S2 {
    const float4 *RHf, *Gf, *Z, *hs;
    const float4 *UrP;
    const float2 *UrB;
    const float4 *bias;
    float4 *ht, *hfnew, *out;
};

__global__ void __launch_bounds__(64) k_stage2(S2 A0, S2 A1, int t) {
    __shared__ ulonglong2 s_AfP[NT * Nn];
    __shared__ ulonglong2 s_AfB2[Nn * (NT / 2)];
    __shared__ ull s_q0[NT * Hh], s_q1[NT * Hh];
    const S2 a = blockIdx.z ? A1 : A0;
    const int tid = threadIdx.x, b = blockIdx.y, n0 = blockIdx.x * NT;
    load_tiles(tid, n0, s_AfP, s_AfB2);
    __syncthreads();

    const int c = tid & 31, half = tid >> 5;
    {
        ull d0[NT], d1[NT];
        #pragma unroll
        for (int j = 0; j < NT; j++) { d0[j] = 0; d1[j] = 0; }
        const float4* in = a.RHf + (size_t)b * Nn * Hh + c;
        agg_m(in, Hh, half * (Nn / 2), half * (Nn / 2) + Nn / 2, s_AfP, s_AfB2, d0, d1);
        if (half == 0) {
            #pragma unroll
            for (int j = 0; j < NT; j++) { s_q0[j * Hh + c] = d0[j]; s_q1[j * Hh + c] = d1[j]; }
        }
        __syncthreads();
        if (half == 1) {
            #pragma unroll
            for (int j = 0; j < NT; j++) {
                s_q0[j * Hh + c] = fadd2(s_q0[j * Hh + c], d0[j]);
                s_q1[j * Hh + c] = fadd2(s_q1[j * Hh + c], d1[j]);
            }
        }
        __syncthreads();
    }

    const int h = tid & 31, g = tid >> 5;
    ull t0[5], t1[5];
    #pragma unroll
    for (int k = 0; k < 5; k++) {
        ulonglong2 gv = *(const ulonglong2*)&a.Gf[(b * Nn + n0 + g * 5 + k) * Hh + h];
        t0[k] = gv.x; t1[k] = gv.y;
    }
    const ulonglong2* UrP = (const ulonglong2*)a.UrP;
    for (int j = 0; j < Hh; j++) {
        int wi = j * Hh + h;
        ulonglong2 ur = UrP[wi]; ull urb = f2u(a.UrB[wi].x, a.UrB[wi].y);
        #pragma unroll
        for (int k = 0; k < 5; k++) {
            int i = (g * 5 + k) * Hh + j;
            ull q0 = s_q0[i], q1 = s_q1[i], q2 = swap2(q1);
            ffma2(t0[k], ur.x, q0); ffma2(t1[k], ur.y, q1); ffma2(t1[k], urb, q2);
        }
    }
    const float4 bh = a.bias[2 * Hh + h];
    #pragma unroll
    for (int k = 0; k < 5; k++) {
        int n = n0 + g * 5 + k;
        int idx = (b * Nn + n) * Hh + h;
        float tt[4];
        ifft4p(t0[k], t1[k], tt);
        float4 z = a.Z[idx], hv = a.hs[idx];
        float4 hn;
        hn.x = z.x * hv.x + (1.f - z.x) * tanhf(tt[0] + bh.x);
        hn.y = z.y * hv.y + (1.f - z.y) * tanhf(tt[1] + bh.y);
        hn.z = z.z * hv.z + (1.f - z.z) * tanhf(tt[2] + bh.z);
        hn.w = z.w * hv.w + (1.f - z.w) * tanhf(tt[3] + bh.w);
        a.ht[idx] = hn;
        float4 s = fft4(hn.x, hn.y, hn.z, hn.w);
        a.hfnew[idx] = make_float4(s.x, s.w, s.y, s.z);
        if (a.out) a.out[((b * Tt + t) * Nn + n) * Hh + h] = hn;
    }
}

__global__ void k_hlast(float4* __restrict__ out) {
    int i = blockIdx.x * blockDim.x + threadIdx.x;
    if (i >= 2 * BNH) return;
    out[OUTE / 4 + i] = (i < BNH) ? g_ht[0][1][i] : g_ht[1][1][i - BNH];
}

// ---------------- host ----------------
extern "C" void kernel_launch(void* const* d_in, const int* in_sizes, int n_in,
                              void* d_out, int out_size) {
    const float* inputs = (const float*)d_in[0];
    const float* U      = (const float*)d_in[1];
    const float4* B0p   = (const float4*)d_in[7];
    const float4* B1p   = (const float4*)d_in[13];

    void *pWP, *pWB, *pXf, *phf, *pht, *pz4, *pZ, *pRH, *pG;
    cudaGetSymbolAddress(&pWP, g_WP);
    cudaGetSymbolAddress(&pWB, g_WB);
    cudaGetSymbolAddress(&pXf, g_Xf);
    cudaGetSymbolAddress(&phf, g_hf);
    cudaGetSymbolAddress(&pht, g_ht);
    cudaGetSymbolAddress(&pz4, g_z4);
    cudaGetSymbolAddress(&pZ,  g_Zg);
    cudaGetSymbolAddress(&pRH, g_RH);
    cudaGetSymbolAddress(&pG,  g_Gf);

    auto WPi = [&](int i) { return (const float4*)pWP + (size_t)i * Hh * Hh; };
    auto WBi = [&](int i) { return (const float2*)pWB + (size_t)i * Hh * Hh; };
    float4* Xf = (float4*)pXf;
    float4* hf[2][2]; float4* ht[2][2];
    for (int l = 0; l < 2; l++)
        for (int u = 0; u < 2; u++) {
            hf[l][u] = (float4*)phf + ((size_t)l * 2 + u) * BNH;
            ht[l][u] = (float4*)pht + ((size_t)l * 2 + u) * BNH;
        }
    float4* z4 = (float4*)pz4;
    float4* Zl[2] = {(float4*)pZ, (float4*)pZ + BNH};
    float4* RHl[2] = {(float4*)pRH, (float4*)pRH + BNH};
    float4* Gl[2] = {(float4*)pG, (float4*)pG + BNH};
    float4* out = (float4*)d_out;

    k_init<<<(BNH + 255) / 256, 256>>>();
    k_adj_raw<<<(Nn * Nn + 127) / 128, 128>>>(U);
    k_softmax<<<dim3(Nn, Rr), 256>>>();
    k_adj_fft<<<(Nn * Nn + 127) / 128, 128>>>();
    k_wfft_all<<<(3 * Ff * Hh + 7 * Hh * Hh + 127) / 128, 128>>>(
        (const float*)d_in[2], (const float*)d_in[3], (const float*)d_in[4],
        (const float*)d_in[5], (const float*)d_in[6],
        (const float*)d_in[8], (const float*)d_in[9], (const float*)d_in[10],
        (const float*)d_in[11], (const float*)d_in[12]);
    k_xfft<<<(Tt * Bb * Nn * Ff + 255) / 256, 256>>>(inputs);

    auto mkS1 = [&](int L, int t, int s) -> S1 {
        S1 a;
        if (L == 0) {
            a.Xf = Xf + (size_t)t * Bb * Nn * Ff;
            a.Fin = Ff;
            a.Hf = (t == 0) ? z4 : hf[0][s];
            a.hs = (t == 0) ? z4 : ht[0][s];
            a.WzP = WPi(0); a.WrP = WPi(1); a.WhP = WPi(2); a.UzP = WPi(3); a.UrP = WPi(4);
            a.WzB = WBi(0); a.WrB = WBi(1); a.WhB = WBi(2); a.UzB = WBi(3); a.UrB = WBi(4);
            a.bias = B0p; a.Z = Zl[0]; a.RHf = RHl[0]; a.Gf = Gl[0];
        } else {
            a.Xf = hf[0][s];
            a.Fin = Hh;
            a.Hf = (t == 0) ? z4 : hf[1][s];
            a.hs = (t == 0) ? z4 : ht[1][s];
            a.WzP = WPi(5); a.WrP = WPi(6); a.WhP = WPi(7); a.UzP = WPi(8); a.UrP = WPi(9);
            a.WzB = WBi(5); a.WrB = WBi(6); a.WhB = WBi(7); a.UzB = WBi(8); a.UrB = WBi(9);
            a.bias = B1p; a.Z = Zl[1]; a.RHf = RHl[1]; a.Gf = Gl[1];
        }
        return a;
    };
    auto mkS2 = [&](int L, int t, int s, int d) -> S2 {
        S2 a;
        if (L == 0) {
            a.RHf = RHl[0]; a.Gf = Gl[0]; a.Z = Zl[0];
            a.hs = (t == 0) ? z4 : ht[0][s];
            a.UrP = WPi(4); a.UrB = WBi(4); a.bias = B0p;
            a.ht = ht[0][d]; a.hfnew = hf[0][d]; a.out = nullptr;
        } else {
            a.RHf = RHl[1]; a.Gf = Gl[1]; a.Z = Zl[1];
            a.hs = (t == 0) ? z4 : ht[1][s];
            a.UrP = WPi(9); a.UrB = WBi(9); a.bias = B1p;
            a.ht = ht[1][d]; a.hfnew = hf[1][d]; a.out = out;
        }
        return a;
    };

    const dim3 blk(64);

    // t = 0: layer1 consumes CURRENT layer0 output -> sequential
    { S1 a = mkS1(0, 0, 0);    k_stage1<<<dim3(NTILES, Bb, 1), blk>>>(a, a); }
    { S2 a = mkS2(0, 0, 0, 0); k_stage2<<<dim3(NTILES, Bb, 1), blk>>>(a, a, 0); }
    { S1 a = mkS1(1, 0, 0);    k_stage1<<<dim3(NTILES, Bb, 1), blk>>>(a, a); }
    { S2 a = mkS2(1, 0, 0, 0); k_stage2<<<dim3(NTILES, Bb, 1), blk>>>(a, a, 0); }

    // t >= 1: layers independent -> merged via blockIdx.z
    for (int t = 1; t < Tt; t++) {
        int s = (t - 1) & 1, d = t & 1;
        S1 a0 = mkS1(0, t, s), a1 = mkS1(1, t, s);
        k_stage1<<<dim3(NTILES, Bb, 2), blk>>>(a0, a1);
        S2 c0 = mkS2(0, t, s, d), c1 = mkS2(1, t, s, d);
        k_stage2<<<dim3(NTILES, Bb, 2), blk>>>(c0, c1, t);
    }

    k_hlast<<<(2 * BNH + 255) / 256, 256>>>(out);
}

// round 8
// speedup vs baseline: 1.1647x; 1.1647x over previous
#include <cuda_runtime.h>
#include <math.h>

typedef unsigned long long ull;

#define Bb 32
#define Tt 8
#define Nn 150
#define Ff 16
#define Hh 32
#define Rr 4
#define Ee 16
#define NT 6
#define NTILES 25
#define NB 2

#define BNH  (Bb*Nn*Hh)
#define OUTE (Bb*Tt*Nn*Hh*Rr)

// ---------------- device state ----------------
__device__ float4 g_AfP[Nn*Nn];          // table: (s.x, s.w, s.y, s.y)
__device__ float2 g_AfB[Nn*Nn];          // table: (-s.z, s.z)
__device__ float  g_adj[Nn*Nn*Rr];
__device__ float4 g_WP[10][Hh*Hh];       // weight tables, same packing
__device__ float2 g_WB[10][Hh*Hh];
__device__ float4 g_Xf[Tt*Bb*Nn*Ff];     // variable layout: (S0, S2, Re, Im)
__device__ float4 g_hf[2][2][BNH];       // spectral hidden [layer][buf]
__device__ float4 g_ht[2][2][BNH];       // time-domain hidden
__device__ float4 g_z4[BNH];             // zeros
__device__ float4 g_Zg[2][BNH];
__device__ float4 g_RH[2][BNH];          // fft(R*H) variable layout
__device__ float4 g_Gf[2][BNH];          // candidate stash (pair layout)

// ---------------- packed f32x2 helpers ----------------
__device__ __forceinline__ void ffma2(ull& d, ull a, ull b) {
    asm("fma.rn.f32x2 %0, %1, %2, %0;" : "+l"(d) : "l"(a), "l"(b));
}
__device__ __forceinline__ ull fadd2(ull a, ull b) {
    ull r; asm("add.rn.f32x2 %0, %1, %2;" : "=l"(r) : "l"(a), "l"(b)); return r;
}
__device__ __forceinline__ float2 u2f(ull v) {
    float2 r; asm("mov.b64 {%0, %1}, %2;" : "=f"(r.x), "=f"(r.y) : "l"(v)); return r;
}
__device__ __forceinline__ ull f2u(float a, float b) {
    ull v; asm("mov.b64 %0, {%1, %2};" : "=l"(v) : "f"(a), "f"(b)); return v;
}
__device__ __forceinline__ ull swap2(ull v) {
    float2 t = u2f(v); return f2u(t.y, t.x);
}

// ---------------- FFT helpers (jnp convention, R=4) ----------------
__device__ __forceinline__ float4 fft4(float x0, float x1, float x2, float x3) {
    return make_float4(x0 + x1 + x2 + x3, x0 - x2, x3 - x1, x0 - x1 + x2 - x3);
}
__device__ __forceinline__ void ifft4p(ull d0, ull d1, float* x) {
    float2 a = u2f(d0), b = u2f(d1);
    x[0] = 0.25f * (a.x + 2.f * b.x + a.y);
    x[1] = 0.25f * (a.x - 2.f * b.y - a.y);
    x[2] = 0.25f * (a.x - 2.f * b.x + a.y);
    x[3] = 0.25f * (a.x + 2.f * b.y - a.y);
}
__device__ __forceinline__ float sigm(float v) { return 1.f / (1.f + expf(-v)); }

// ---------------- precompute ----------------
__global__ void k_init() {
    int i = blockIdx.x * blockDim.x + threadIdx.x;
    if (i < BNH) g_z4[i] = make_float4(0.f, 0.f, 0.f, 0.f);
}

__global__ void k_adj_raw(const float* __restrict__ U) {
    int idx = blockIdx.x * blockDim.x + threadIdx.x;
    if (idx >= Nn * Nn) return;
    int n = idx / Nn, m = idx % Nn;
    float4 g = make_float4(0.f, 0.f, 0.f, 0.f);
    for (int e = 0; e < Ee; e++) {
        const float* un = U + (n * Ee + e) * Rr;
        const float* um = U + (m * Ee + e) * Rr;
        float4 a = fft4(un[0], un[1], un[2], un[3]);
        float4 b = fft4(um[0], um[1], um[2], um[3]);
        g.x += a.x * b.x;
        g.y += a.y * b.y - a.z * b.z;
        g.z += a.y * b.z + a.z * b.y;
        g.w += a.w * b.w;
    }
    float x0 = 0.25f * (g.x + 2.f * g.y + g.w);
    float x1 = 0.25f * (g.x - 2.f * g.z - g.w);
    float x2 = 0.25f * (g.x - 2.f * g.y + g.w);
    float x3 = 0.25f * (g.x + 2.f * g.z - g.w);
    g_adj[idx * 4 + 0] = fmaxf(x0, 0.f);
    g_adj[idx * 4 + 1] = fmaxf(x1, 0.f);
    g_adj[idx * 4 + 2] = fmaxf(x2, 0.f);
    g_adj[idx * 4 + 3] = fmaxf(x3, 0.f);
}

__global__ void k_softmax() {
    int n = blockIdx.x, r = blockIdx.y;
    int tid = threadIdx.x;
    __shared__ float red[256];
    float v = (tid < Nn) ? g_adj[(n * Nn + tid) * Rr + r] : -1e30f;
    red[tid] = v;
    __syncthreads();
    for (int s = 128; s > 0; s >>= 1) {
        if (tid < s) red[tid] = fmaxf(red[tid], red[tid + s]);
        __syncthreads();
    }
    float mx = red[0];
    __syncthreads();
    float e = (tid < Nn) ? expf(v - mx) : 0.f;
    red[tid] = e;
    __syncthreads();
    for (int s = 128; s > 0; s >>= 1) {
        if (tid < s) red[tid] += red[tid + s];
        __syncthreads();
    }
    float inv = 1.f / red[0];
    if (tid < Nn) g_adj[(n * Nn + tid) * Rr + r] = e * inv;
}

__global__ void k_adj_fft() {
    int idx = blockIdx.x * blockDim.x + threadIdx.x;
    if (idx >= Nn * Nn) return;
    const float* a = g_adj + idx * 4;
    float4 s = fft4(a[0], a[1], a[2], a[3]);
    g_AfP[idx] = make_float4(s.x, s.w, s.y, s.y);
    g_AfB[idx] = make_float2(-s.z, s.z);
}

__global__ void k_wfft_all(const float* p0, const float* p1, const float* p2,
                           const float* p3, const float* p4, const float* p5,
                           const float* p6, const float* p7, const float* p8,
                           const float* p9) {
    int idx = blockIdx.x * blockDim.x + threadIdx.x;
    const int small = Ff * Hh, big = Hh * Hh;
    if (idx >= 3 * small + 7 * big) return;
    int wi, off;
    if (idx < 3 * small) { wi = idx / small; off = idx % small; }
    else { int j = idx - 3 * small; wi = 3 + j / big; off = j % big; }
    const float* ps[10] = {p0, p1, p2, p3, p4, p5, p6, p7, p8, p9};
    const float* w = ps[wi] + off * Rr;
    float4 s = fft4(w[0], w[1], w[2], w[3]);
    g_WP[wi][off] = make_float4(s.x, s.w, s.y, s.y);
    g_WB[wi][off] = make_float2(-s.z, s.z);
}

__global__ void k_xfft(const float* __restrict__ inputs) {
    int idx = blockIdx.x * blockDim.x + threadIdx.x;
    if (idx >= Tt * Bb * Nn * Ff) return;
    int f = idx % Ff;
    int n = (idx / Ff) % Nn;
    int b = (idx / (Ff * Nn)) % Bb;
    int t = idx / (Ff * Nn * Bb);
    const float* p = inputs + ((((size_t)b * Tt + t) * Nn + n) * Ff + f) * Rr;
    float4 s = fft4(p[0], p[1], p[2], p[3]);
    g_Xf[idx] = make_float4(s.x, s.w, s.y, s.z);
}

// ---------------- shared tile loader (128 threads) ----------------
__device__ __forceinline__ void load_tiles(int tid, int n0,
        ulonglong2* s_AfP, ulonglong2* s_AfB2) {
    const ulonglong2* AfP = (const ulonglong2*)g_AfP;
    for (int i = tid; i < NT * Nn; i += 128) {
        int j = i / Nn, m = i % Nn;
        s_AfP[i] = AfP[(n0 + j) * Nn + m];
    }
    for (int i = tid; i < Nn * (NT / 2); i += 128) {
        int m = i / (NT / 2), jp = i % (NT / 2);
        float2 b0 = g_AfB[(n0 + 2 * jp) * Nn + m];
        float2 b1 = g_AfB[(n0 + 2 * jp + 1) * Nn + m];
        s_AfB2[i] = make_ulonglong2(f2u(b0.x, b0.y), f2u(b1.x, b1.y));
    }
}

// accumulate NT rows for one channel over m range
__device__ __forceinline__ void agg_m(const float4* in, int stride, int m0, int m1,
        const ulonglong2* s_AfP, const ulonglong2* s_AfB2, ull* d0, ull* d1) {
    for (int m = m0; m < m1; m++) {
        float4 v = in[(size_t)m * stride];
        ull q0 = f2u(v.x, v.y), q1 = f2u(v.z, v.w), q2 = f2u(v.w, v.z);
        #pragma unroll
        for (int jp = 0; jp < NT / 2; jp++) {
            ulonglong2 pb = s_AfB2[m * (NT / 2) + jp];
            ulonglong2 p = s_AfP[(2 * jp) * Nn + m];
            ffma2(d0[2 * jp], p.x, q0);
            ffma2(d1[2 * jp], p.y, q1);
            ffma2(d1[2 * jp], pb.x, q2);
            p = s_AfP[(2 * jp + 1) * Nn + m];
            ffma2(d0[2 * jp + 1], p.x, q0);
            ffma2(d1[2 * jp + 1], p.y, q1);
            ffma2(d1[2 * jp + 1], pb.y, q2);
        }
    }
}

// ---------------- stage kernels ----------------
struct S1 {
    const float4 *Xf, *Hf, *hs;
    const float4 *WzP, *WrP, *WhP, *UzP, *UrP;
    const float2 *WzB, *WrB, *WhB, *UzB, *UrB;
    const float4 *bias;
    float4 *Z, *RHf, *Gf;
    int Fin;
};

__global__ void __launch_bounds__(128, 5) k_stage1(S1 A0, S1 A1) {
    __shared__ ulonglong2 s_AfP[NT * Nn];          // 14400 B
    __shared__ ulonglong2 s_AfB2[Nn * (NT / 2)];   // 7200 B
    __shared__ ull s_q0[NB * NT * 64], s_q1[NB * NT * 64];  // 2 x 6144 B
    const S1 a = blockIdx.z ? A1 : A0;
    const int tid = threadIdx.x;
    const int bl = tid >> 6, t64 = tid & 63;
    const int b = blockIdx.y * NB + bl;
    const int n0 = blockIdx.x * NT;
    load_tiles(tid, n0, s_AfP, s_AfB2);
    __syncthreads();

    const int C = a.Fin + Hh;
    if (t64 < C) {
        const float4* in;
        int stride;
        if (t64 < a.Fin) { in = a.Xf + (size_t)b * Nn * a.Fin + t64; stride = a.Fin; }
        else             { in = a.Hf + (size_t)b * Nn * Hh + (t64 - a.Fin); stride = Hh; }
        ull d0[NT], d1[NT];
        #pragma unroll
        for (int j = 0; j < NT; j++) { d0[j] = 0; d1[j] = 0; }
        agg_m(in, stride, 0, Nn, s_AfP, s_AfB2, d0, d1);
        #pragma unroll
        for (int j = 0; j < NT; j++) {
            s_q0[(bl * NT + j) * 64 + t64] = d0[j];
            s_q1[(bl * NT + j) * 64 + t64] = d1[j];
        }
    }
    __syncthreads();

    const int h = t64 & 31, g = t64 >> 5;   // g in {0,1}, rows g*3+k
    ull z0[3], z1[3], r0[3], r1[3], c0[3], c1[3];
    #pragma unroll
    for (int k = 0; k < 3; k++) { z0[k]=0; z1[k]=0; r0[k]=0; r1[k]=0; c0[k]=0; c1[k]=0; }

    const ulonglong2* WzP = (const ulonglong2*)a.WzP;
    const ulonglong2* WrP = (const ulonglong2*)a.WrP;
    const ulonglong2* WhP = (const ulonglong2*)a.WhP;
    for (int f = 0; f < a.Fin; f++) {
        int wi = f * Hh + h;
        ulonglong2 wz = WzP[wi]; ull wzb = f2u(a.WzB[wi].x, a.WzB[wi].y);
        ulonglong2 wr = WrP[wi]; ull wrb = f2u(a.WrB[wi].x, a.WrB[wi].y);
        ulonglong2 wh = WhP[wi]; ull whb = f2u(a.WhB[wi].x, a.WhB[wi].y);
        #pragma unroll
        for (int k = 0; k < 3; k++) {
            int i = (bl * NT + g * 3 + k) * 64 + f;
            ull q0 = s_q0[i], q1 = s_q1[i], q2 = swap2(q1);
            ffma2(z0[k], wz.x, q0); ffma2(z1[k], wz.y, q1); ffma2(z1[k], wzb, q2);
            ffma2(r0[k], wr.x, q0); ffma2(r1[k], wr.y, q1); ffma2(r1[k], wrb, q2);
            ffma2(c0[k], wh.x, q0); ffma2(c1[k], wh.y, q1); ffma2(c1[k], whb, q2);
        }
    }
    const ulonglong2* UzP = (const ulonglong2*)a.UzP;
    const ulonglong2* UrP = (const ulonglong2*)a.UrP;
    for (int j = 0; j < Hh; j++) {
        int wi = j * Hh + h;
        ulonglong2 uz = UzP[wi]; ull uzb = f2u(a.UzB[wi].x, a.UzB[wi].y);
        ulonglong2 ur = UrP[wi]; ull urb = f2u(a.UrB[wi].x, a.UrB[wi].y);
        #pragma unroll
        for (int k = 0; k < 3; k++) {
            int i = (bl * NT + g * 3 + k) * 64 + a.Fin + j;
            ull q0 = s_q0[i], q1 = s_q1[i], q2 = swap2(q1);
            ffma2(z0[k], uz.x, q0); ffma2(z1[k], uz.y, q1); ffma2(z1[k], uzb, q2);
            ffma2(r0[k], ur.x, q0); ffma2(r1[k], ur.y, q1); ffma2(r1[k], urb, q2);
        }
    }

    const float4 bz = a.bias[h], br = a.bias[Hh + h];
    #pragma unroll
    for (int k = 0; k < 3; k++) {
        int idx = (b * Nn + n0 + g * 3 + k) * Hh + h;
        float zt[4], rt[4];
        ifft4p(z0[k], z1[k], zt);
        ifft4p(r0[k], r1[k], rt);
        float4 hv = a.hs[idx];
        a.Z[idx] = make_float4(sigm(zt[0] + bz.x), sigm(zt[1] + bz.y),
                               sigm(zt[2] + bz.z), sigm(zt[3] + bz.w));
        float rh0 = sigm(rt[0] + br.x) * hv.x;
        float rh1 = sigm(rt[1] + br.y) * hv.y;
        float rh2 = sigm(rt[2] + br.z) * hv.z;
        float rh3 = sigm(rt[3] + br.w) * hv.w;
        float4 s = fft4(rh0, rh1, rh2, rh3);
        a.RHf[idx] = make_float4(s.x, s.w, s.y, s.z);
        *(ulonglong2*)&a.Gf[idx] = make_ulonglong2(c0[k], c1[k]);
    }
}

struct S2 {
    const float4 *RHf, *Gf, *Z, *hs;
    const float4 *UrP;
    const float2 *UrB;
    const float4 *bias;
    float4 *ht, *hfnew, *out;
};

__global__ void __launch_bounds__(128, 5) k_stage2(S2 A0, S2 A1, int t) {
    __shared__ ulonglong2 s_AfP[NT * Nn];
    __shared__ ulonglong2 s_AfB2[Nn * (NT / 2)];
    __shared__ ull s_q0[NB * NT * Hh], s_q1[NB * NT * Hh];
    const S2 a = blockIdx.z ? A1 : A0;
    const int tid = threadIdx.x;
    const int bl = tid >> 6, t64 = tid & 63;
    const int b = blockIdx.y * NB + bl;
    const int n0 = blockIdx.x * NT;
    load_tiles(tid, n0, s_AfP, s_AfB2);
    __syncthreads();

    const int c = t64 & 31, half = t64 >> 5;
    {
        ull d0[NT], d1[NT];
        #pragma unroll
        for (int j = 0; j < NT; j++) { d0[j] = 0; d1[j] = 0; }
        const float4* in = a.RHf + (size_t)b * Nn * Hh + c;
        agg_m(in, Hh, half * (Nn / 2), half * (Nn / 2) + Nn / 2, s_AfP, s_AfB2, d0, d1);
        if (half == 0) {
            #pragma unroll
            for (int j = 0; j < NT; j++) {
                s_q0[(bl * NT + j) * Hh + c] = d0[j];
                s_q1[(bl * NT + j) * Hh + c] = d1[j];
            }
        }
        __syncthreads();
        if (half == 1) {
            #pragma unroll
            for (int j = 0; j < NT; j++) {
                int i = (bl * NT + j) * Hh + c;
                s_q0[i] = fadd2(s_q0[i], d0[j]);
                s_q1[i] = fadd2(s_q1[i], d1[j]);
            }
        }
        __syncthreads();
    }

    const int h = t64 & 31, g = t64 >> 5;
    ull t0[3], t1[3];
    #pragma unroll
    for (int k = 0; k < 3; k++) {
        ulonglong2 gv = *(const ulonglong2*)&a.Gf[(b * Nn + n0 + g * 3 + k) * Hh + h];
        t0[k] = gv.x; t1[k] = gv.y;
    }
    const ulonglong2* UrP = (const ulonglong2*)a.UrP;
    for (int j = 0; j < Hh; j++) {
        int wi = j * Hh + h;
        ulonglong2 ur = UrP[wi]; ull urb = f2u(a.UrB[wi].x, a.UrB[wi].y);
        #pragma unroll
        for (int k = 0; k < 3; k++) {
            int i = (bl * NT + g * 3 + k) * Hh + j;
            ull q0 = s_q0[i], q1 = s_q1[i], q2 = swap2(q1);
            ffma2(t0[k], ur.x, q0); ffma2(t1[k], ur.y, q1); ffma2(t1[k], urb, q2);
        }
    }
    const float4 bh = a.bias[2 * Hh + h];
    #pragma unroll
    for (int k = 0; k < 3; k++) {
        int n = n0 + g * 3 + k;
        int idx = (b * Nn + n) * Hh + h;
        float tt[4];
        ifft4p(t0[k], t1[k], tt);
        float4 z = a.Z[idx], hv = a.hs[idx];
        float4 hn;
        hn.x = z.x * hv.x + (1.f - z.x) * tanhf(tt[0] + bh.x);
        hn.y = z.y * hv.y + (1.f - z.y) * tanhf(tt[1] + bh.y);
        hn.z = z.z * hv.z + (1.f - z.z) * tanhf(tt[2] + bh.z);
        hn.w = z.w * hv.w + (1.f - z.w) * tanhf(tt[3] + bh.w);
        a.ht[idx] = hn;
        float4 s = fft4(hn.x, hn.y, hn.z, hn.w);
        a.hfnew[idx] = make_float4(s.x, s.w, s.y, s.z);
        if (a.out) a.out[((b * Tt + t) * Nn + n) * Hh + h] = hn;
    }
}

__global__ void k_hlast(float4* __restrict__ out) {
    int i = blockIdx.x * blockDim.x + threadIdx.x;
    if (i >= 2 * BNH) return;
    out[OUTE / 4 + i] = (i < BNH) ? g_ht[0][1][i] : g_ht[1][1][i - BNH];
}

// ---------------- host ----------------
extern "C" void kernel_launch(void* const* d_in, const int* in_sizes, int n_in,
                              void* d_out, int out_size) {
    const float* inputs = (const float*)d_in[0];
    const float* U      = (const float*)d_in[1];
    const float4* B0p   = (const float4*)d_in[7];
    const float4* B1p   = (const float4*)d_in[13];

    void *pWP, *pWB, *pXf, *phf, *pht, *pz4, *pZ, *pRH, *pG;
    cudaGetSymbolAddress(&pWP, g_WP);
    cudaGetSymbolAddress(&pWB, g_WB);
    cudaGetSymbolAddress(&pXf, g_Xf);
    cudaGetSymbolAddress(&phf, g_hf);
    cudaGetSymbolAddress(&pht, g_ht);
    cudaGetSymbolAddress(&pz4, g_z4);
    cudaGetSymbolAddress(&pZ,  g_Zg);
    cudaGetSymbolAddress(&pRH, g_RH);
    cudaGetSymbolAddress(&pG,  g_Gf);

    auto WPi = [&](int i) { return (const float4*)pWP + (size_t)i * Hh * Hh; };
    auto WBi = [&](int i) { return (const float2*)pWB + (size_t)i * Hh * Hh; };
    float4* Xf = (float4*)pXf;
    float4* hf[2][2]; float4* ht[2][2];
    for (int l = 0; l < 2; l++)
        for (int u = 0; u < 2; u++) {
            hf[l][u] = (float4*)phf + ((size_t)l * 2 + u) * BNH;
            ht[l][u] = (float4*)pht + ((size_t)l * 2 + u) * BNH;
        }
    float4* z4 = (float4*)pz4;
    float4* Zl[2] = {(float4*)pZ, (float4*)pZ + BNH};
    float4* RHl[2] = {(float4*)pRH, (float4*)pRH + BNH};
    float4* Gl[2] = {(float4*)pG, (float4*)pG + BNH};
    float4* out = (float4*)d_out;

    k_init<<<(BNH + 255) / 256, 256>>>();
    k_adj_raw<<<(Nn * Nn + 127) / 128, 128>>>(U);
    k_softmax<<<dim3(Nn, Rr), 256>>>();
    k_adj_fft<<<(Nn * Nn + 127) / 128, 128>>>();
    k_wfft_all<<<(3 * Ff * Hh + 7 * Hh * Hh + 127) / 128, 128>>>(
        (const float*)d_in[2], (const float*)d_in[3], (const float*)d_in[4],
        (const float*)d_in[5], (const float*)d_in[6],
        (const float*)d_in[8], (const float*)d_in[9], (const float*)d_in[10],
        (const float*)d_in[11], (const float*)d_in[12]);
    k_xfft<<<(Tt * Bb * Nn * Ff + 255) / 256, 256>>>(inputs);

    auto mkS1 = [&](int L, int t, int s) -> S1 {
        S1 a;
        if (L == 0) {
            a.Xf = Xf + (size_t)t * Bb * Nn * Ff;
            a.Fin = Ff;
            a.Hf = (t == 0) ? z4 : hf[0][s];
            a.hs = (t == 0) ? z4 : ht[0][s];
            a.WzP = WPi(0); a.WrP = WPi(1); a.WhP = WPi(2); a.UzP = WPi(3); a.UrP = WPi(4);
            a.WzB = WBi(0); a.WrB = WBi(1); a.WhB = WBi(2); a.UzB = WBi(3); a.UrB = WBi(4);
            a.bias = B0p; a.Z = Zl[0]; a.RHf = RHl[0]; a.Gf = Gl[0];
        } else {
            a.Xf = hf[0][s];
            a.Fin = Hh;
            a.Hf = (t == 0) ? z4 : hf[1][s];
            a.hs = (t == 0) ? z4 : ht[1][s];
            a.WzP = WPi(5); a.WrP = WPi(6); a.WhP = WPi(7); a.UzP = WPi(8); a.UrP = WPi(9);
            a.WzB = WBi(5); a.WrB = WBi(6); a.WhB = WBi(7); a.UzB = WBi(8); a.UrB = WBi(9);
            a.bias = B1p; a.Z = Zl[1]; a.RHf = RHl[1]; a.Gf = Gl[1];
        }
        return a;
    };
    auto mkS2 = [&](int L, int t, int s, int d) -> S2 {
        S2 a;
        if (L == 0) {
            a.RHf = RHl[0]; a.Gf = Gl[0]; a.Z = Zl[0];
            a.hs = (t == 0) ? z4 : ht[0][s];
            a.UrP = WPi(4); a.UrB = WBi(4); a.bias = B0p;
            a.ht = ht[0][d]; a.hfnew = hf[0][d]; a.out = nullptr;
        } else {
            a.RHf = RHl[1]; a.Gf = Gl[1]; a.Z = Zl[1];
            a.hs = (t == 0) ? z4 : ht[1][s];
            a.UrP = WPi(9); a.UrB = WBi(9); a.bias = B1p;
            a.ht = ht[1][d]; a.hfnew = hf[1][d]; a.out = out;
        }
        return a;
    };

    const dim3 blk(128);
    const int GY = Bb / NB;   // 16

    // t = 0: layer1 consumes CURRENT layer0 output -> sequential
    { S1 a = mkS1(0, 0, 0);    k_stage1<<<dim3(NTILES, GY, 1), blk>>>(a, a); }
    { S2 a = mkS2(0, 0, 0, 0); k_stage2<<<dim3(NTILES, GY, 1), blk>>>(a, a, 0); }
    { S1 a = mkS1(1, 0, 0);    k_stage1<<<dim3(NTILES, GY, 1), blk>>>(a, a); }
    { S2 a = mkS2(1, 0, 0, 0); k_stage2<<<dim3(NTILES, GY, 1), blk>>>(a, a, 0); }

    // t >= 1: layers independent -> merged via blockIdx.z
    for (int t = 1; t < Tt; t++) {
        int s = (t - 1) & 1, d = t & 1;
        S1 a0 = mkS1(0, t, s), a1 = mkS1(1, t, s);
        k_stage1<<<dim3(NTILES, GY, 2), blk>>>(a0, a1);
        S2 c0 = mkS2(0, t, s, d), c1 = mkS2(1, t, s, d);
        k_stage2<<<dim3(NTILES, GY, 2), blk>>>(c0, c1, t);
    }

    k_hlast<<<(2 * BNH + 255) / 256, 256>>>(out);
}

// round 9
// speedup vs baseline: 1.3072x; 1.1223x over previous
#include <cuda_runtime.h>
#include <math.h>

typedef unsigned long long ull;

#define Bb 32
#define Tt 8
#define Nn 150
#define Ff 16
#define Hh 32
#define Rr 4
#define Ee 16
#define NT 6
#define NTILES 25
#define NB 2

#define BNH  (Bb*Nn*Hh)
#define OUTE (Bb*Tt*Nn*Hh*Rr)

// ---------------- device state ----------------
__device__ float4 g_AfP[Nn*Nn];          // table: (s.x, s.w, s.y, s.y)
__device__ float2 g_AfB[Nn*Nn];          // table: (-s.z, s.z)
__device__ float  g_adj[Nn*Nn*Rr];
__device__ float4 g_WP[10][Hh*Hh];       // weight tables, same packing
__device__ float2 g_WB[10][Hh*Hh];
__device__ float4 g_Xf[Tt*Bb*Nn*Ff];     // variable layout: (S0, S2, Re, Im)
__device__ float4 g_hf[2][2][BNH];       // spectral hidden [layer][buf]
__device__ float4 g_ht[2][2][BNH];       // time-domain hidden
__device__ float4 g_z4[BNH];             // zeros
__device__ float4 g_Zg[2][BNH];
__device__ float4 g_RH[2][BNH];          // fft(R*H) variable layout
__device__ float4 g_Gf[2][BNH];          // candidate stash (pair layout)

// ---------------- packed f32x2 helpers ----------------
__device__ __forceinline__ void ffma2(ull& d, ull a, ull b) {
    asm("fma.rn.f32x2 %0, %1, %2, %0;" : "+l"(d) : "l"(a), "l"(b));
}
__device__ __forceinline__ ull fadd2(ull a, ull b) {
    ull r; asm("add.rn.f32x2 %0, %1, %2;" : "=l"(r) : "l"(a), "l"(b)); return r;
}
__device__ __forceinline__ float2 u2f(ull v) {
    float2 r; asm("mov.b64 {%0, %1}, %2;" : "=f"(r.x), "=f"(r.y) : "l"(v)); return r;
}
__device__ __forceinline__ ull f2u(float a, float b) {
    ull v; asm("mov.b64 %0, {%1, %2};" : "=l"(v) : "f"(a), "f"(b)); return v;
}
__device__ __forceinline__ ull swap2(ull v) {
    float2 t = u2f(v); return f2u(t.y, t.x);
}

// ---------------- FFT helpers (jnp convention, R=4) ----------------
__device__ __forceinline__ float4 fft4(float x0, float x1, float x2, float x3) {
    return make_float4(x0 + x1 + x2 + x3, x0 - x2, x3 - x1, x0 - x1 + x2 - x3);
}
__device__ __forceinline__ void ifft4p(ull d0, ull d1, float* x) {
    float2 a = u2f(d0), b = u2f(d1);
    x[0] = 0.25f * (a.x + 2.f * b.x + a.y);
    x[1] = 0.25f * (a.x - 2.f * b.y - a.y);
    x[2] = 0.25f * (a.x - 2.f * b.x + a.y);
    x[3] = 0.25f * (a.x + 2.f * b.y - a.y);
}
__device__ __forceinline__ float sigm(float v) { return 1.f / (1.f + expf(-v)); }

// ---------------- prep kernels (3 launches total) ----------------
__global__ void k_adj_raw(const float* __restrict__ U) {
    int idx = blockIdx.x * blockDim.x + threadIdx.x;
    if (idx >= Nn * Nn) return;
    int n = idx / Nn, m = idx % Nn;
    float4 g = make_float4(0.f, 0.f, 0.f, 0.f);
    for (int e = 0; e < Ee; e++) {
        const float* un = U + (n * Ee + e) * Rr;
        const float* um = U + (m * Ee + e) * Rr;
        float4 a = fft4(un[0], un[1], un[2], un[3]);
        float4 b = fft4(um[0], um[1], um[2], um[3]);
        g.x += a.x * b.x;
        g.y += a.y * b.y - a.z * b.z;
        g.z += a.y * b.z + a.z * b.y;
        g.w += a.w * b.w;
    }
    float x0 = 0.25f * (g.x + 2.f * g.y + g.w);
    float x1 = 0.25f * (g.x - 2.f * g.z - g.w);
    float x2 = 0.25f * (g.x - 2.f * g.y + g.w);
    float x3 = 0.25f * (g.x + 2.f * g.z - g.w);
    g_adj[idx * 4 + 0] = fmaxf(x0, 0.f);
    g_adj[idx * 4 + 1] = fmaxf(x1, 0.f);
    g_adj[idx * 4 + 2] = fmaxf(x2, 0.f);
    g_adj[idx * 4 + 3] = fmaxf(x3, 0.f);
}

__global__ void k_softmax() {
    int n = blockIdx.x, r = blockIdx.y;
    int tid = threadIdx.x;
    __shared__ float red[256];
    float v = (tid < Nn) ? g_adj[(n * Nn + tid) * Rr + r] : -1e30f;
    red[tid] = v;
    __syncthreads();
    for (int s = 128; s > 0; s >>= 1) {
        if (tid < s) red[tid] = fmaxf(red[tid], red[tid + s]);
        __syncthreads();
    }
    float mx = red[0];
    __syncthreads();
    float e = (tid < Nn) ? expf(v - mx) : 0.f;
    red[tid] = e;
    __syncthreads();
    for (int s = 128; s > 0; s >>= 1) {
        if (tid < s) red[tid] += red[tid + s];
        __syncthreads();
    }
    float inv = 1.f / red[0];
    if (tid < Nn) g_adj[(n * Nn + tid) * Rr + r] = e * inv;
}

// fused: X fft + zero init + adj fft + weight fft
#define XT (Tt*Bb*Nn*Ff)
__global__ void k_misc(const float* __restrict__ inputs,
                       const float* p0, const float* p1, const float* p2,
                       const float* p3, const float* p4, const float* p5,
                       const float* p6, const float* p7, const float* p8,
                       const float* p9) {
    int idx = blockIdx.x * blockDim.x + threadIdx.x;
    if (idx < XT) {
        int f = idx % Ff;
        int n = (idx / Ff) % Nn;
        int b = (idx / (Ff * Nn)) % Bb;
        int t = idx / (Ff * Nn * Bb);
        const float* p = inputs + ((((size_t)b * Tt + t) * Nn + n) * Ff + f) * Rr;
        float4 s = fft4(p[0], p[1], p[2], p[3]);
        g_Xf[idx] = make_float4(s.x, s.w, s.y, s.z);
        return;
    }
    idx -= XT;
    if (idx < BNH) {
        g_z4[idx] = make_float4(0.f, 0.f, 0.f, 0.f);
        return;
    }
    idx -= BNH;
    if (idx < Nn * Nn) {
        const float* a = g_adj + idx * 4;
        float4 s = fft4(a[0], a[1], a[2], a[3]);
        g_AfP[idx] = make_float4(s.x, s.w, s.y, s.y);
        g_AfB[idx] = make_float2(-s.z, s.z);
        return;
    }
    idx -= Nn * Nn;
    const int small = Ff * Hh, big = Hh * Hh;
    if (idx >= 3 * small + 7 * big) return;
    int wi, off;
    if (idx < 3 * small) { wi = idx / small; off = idx % small; }
    else { int j = idx - 3 * small; wi = 3 + j / big; off = j % big; }
    const float* ps[10] = {p0, p1, p2, p3, p4, p5, p6, p7, p8, p9};
    const float* w = ps[wi] + off * Rr;
    float4 s = fft4(w[0], w[1], w[2], w[3]);
    g_WP[wi][off] = make_float4(s.x, s.w, s.y, s.y);
    g_WB[wi][off] = make_float2(-s.z, s.z);
}

// ---------------- shared tile loader (256 threads) ----------------
__device__ __forceinline__ void load_tiles(int tid, int n0,
        ulonglong2* s_AfP, ulonglong2* s_AfB2) {
    const ulonglong2* AfP = (const ulonglong2*)g_AfP;
    for (int i = tid; i < NT * Nn; i += 256) {
        int j = i / Nn, m = i % Nn;
        s_AfP[i] = AfP[(n0 + j) * Nn + m];
    }
    for (int i = tid; i < Nn * (NT / 2); i += 256) {
        int m = i / (NT / 2), jp = i % (NT / 2);
        float2 b0 = g_AfB[(n0 + 2 * jp) * Nn + m];
        float2 b1 = g_AfB[(n0 + 2 * jp + 1) * Nn + m];
        s_AfB2[i] = make_ulonglong2(f2u(b0.x, b0.y), f2u(b1.x, b1.y));
    }
}

// accumulate NT rows for one channel over m range
__device__ __forceinline__ void agg_m(const float4* in, int stride, int m0, int m1,
        const ulonglong2* s_AfP, const ulonglong2* s_AfB2, ull* d0, ull* d1) {
    for (int m = m0; m < m1; m++) {
        float4 v = in[(size_t)m * stride];
        ull q0 = f2u(v.x, v.y), q1 = f2u(v.z, v.w), q2 = f2u(v.w, v.z);
        #pragma unroll
        for (int jp = 0; jp < NT / 2; jp++) {
            ulonglong2 pb = s_AfB2[m * (NT / 2) + jp];
            ulonglong2 p = s_AfP[(2 * jp) * Nn + m];
            ffma2(d0[2 * jp], p.x, q0);
            ffma2(d1[2 * jp], p.y, q1);
            ffma2(d1[2 * jp], pb.x, q2);
            p = s_AfP[(2 * jp + 1) * Nn + m];
            ffma2(d0[2 * jp + 1], p.x, q0);
            ffma2(d1[2 * jp + 1], p.y, q1);
            ffma2(d1[2 * jp + 1], pb.y, q2);
        }
    }
}

// ---------------- stage kernels: 256 threads, both layers per block ----------------
struct S1 {
    const float4 *Xf, *Hf, *hs;
    const float4 *WzP, *WrP, *WhP, *UzP, *UrP;
    const float2 *WzB, *WrB, *WhB, *UzB, *UrB;
    const float4 *bias;
    float4 *Z, *RHf, *Gf;
    int Fin;
};

__global__ void __launch_bounds__(256, 3) k_stage1(S1 A0, S1 A1, int lmask) {
    __shared__ ulonglong2 s_AfP[NT * Nn];            // 14400 B
    __shared__ ulonglong2 s_AfB2[Nn * (NT / 2)];     // 7200 B
    __shared__ ull s_q0[4 * NT * 64], s_q1[4 * NT * 64];  // 2 x 12288 B
    const int tid = threadIdx.x;
    const int layer = tid >> 7, hid = tid & 127;
    const int bl = hid >> 6, t64 = hid & 63;
    const int b = blockIdx.y * NB + bl;
    const int n0 = blockIdx.x * NT;
    load_tiles(tid, n0, s_AfP, s_AfB2);
    __syncthreads();
    if (!(lmask & (1 << layer))) return;
    const S1 a = layer ? A1 : A0;
    const int qb = (layer * NB + bl) * NT;

    const int C = a.Fin + Hh;
    if (t64 < C) {
        const float4* in;
        int stride;
        if (t64 < a.Fin) { in = a.Xf + (size_t)b * Nn * a.Fin + t64; stride = a.Fin; }
        else             { in = a.Hf + (size_t)b * Nn * Hh + (t64 - a.Fin); stride = Hh; }
        ull d0[NT], d1[NT];
        #pragma unroll
        for (int j = 0; j < NT; j++) { d0[j] = 0; d1[j] = 0; }
        agg_m(in, stride, 0, Nn, s_AfP, s_AfB2, d0, d1);
        #pragma unroll
        for (int j = 0; j < NT; j++) {
            s_q0[(qb + j) * 64 + t64] = d0[j];
            s_q1[(qb + j) * 64 + t64] = d1[j];
        }
    }
    __syncthreads();

    const int h = t64 & 31, g = t64 >> 5;   // g in {0,1}, rows g*3+k
    ull z0[3], z1[3], r0[3], r1[3], c0[3], c1[3];
    #pragma unroll
    for (int k = 0; k < 3; k++) { z0[k]=0; z1[k]=0; r0[k]=0; r1[k]=0; c0[k]=0; c1[k]=0; }

    const ulonglong2* WzP = (const ulonglong2*)a.WzP;
    const ulonglong2* WrP = (const ulonglong2*)a.WrP;
    const ulonglong2* WhP = (const ulonglong2*)a.WhP;
    for (int f = 0; f < a.Fin; f++) {
        int wi = f * Hh + h;
        ulonglong2 wz = WzP[wi]; ull wzb = f2u(a.WzB[wi].x, a.WzB[wi].y);
        ulonglong2 wr = WrP[wi]; ull wrb = f2u(a.WrB[wi].x, a.WrB[wi].y);
        ulonglong2 wh = WhP[wi]; ull whb = f2u(a.WhB[wi].x, a.WhB[wi].y);
        #pragma unroll
        for (int k = 0; k < 3; k++) {
            int i = (qb + g * 3 + k) * 64 + f;
            ull q0 = s_q0[i], q1 = s_q1[i], q2 = swap2(q1);
            ffma2(z0[k], wz.x, q0); ffma2(z1[k], wz.y, q1); ffma2(z1[k], wzb, q2);
            ffma2(r0[k], wr.x, q0); ffma2(r1[k], wr.y, q1); ffma2(r1[k], wrb, q2);
            ffma2(c0[k], wh.x, q0); ffma2(c1[k], wh.y, q1); ffma2(c1[k], whb, q2);
        }
    }
    const ulonglong2* UzP = (const ulonglong2*)a.UzP;
    const ulonglong2* UrP = (const ulonglong2*)a.UrP;
    for (int j = 0; j < Hh; j++) {
        int wi = j * Hh + h;
        ulonglong2 uz = UzP[wi]; ull uzb = f2u(a.UzB[wi].x, a.UzB[wi].y);
        ulonglong2 ur = UrP[wi]; ull urb = f2u(a.UrB[wi].x, a.UrB[wi].y);
        #pragma unroll
        for (int k = 0; k < 3; k++) {
            int i = (qb + g * 3 + k) * 64 + a.Fin + j;
            ull q0 = s_q0[i], q1 = s_q1[i], q2 = swap2(q1);
            ffma2(z0[k], uz.x, q0); ffma2(z1[k], uz.y, q1); ffma2(z1[k], uzb, q2);
            ffma2(r0[k], ur.x, q0); ffma2(r1[k], ur.y, q1); ffma2(r1[k], urb, q2);
        }
    }

    const float4 bz = a.bias[h], br = a.bias[Hh + h];
    #pragma unroll
    for (int k = 0; k < 3; k++) {
        int idx = (b * Nn + n0 + g * 3 + k) * Hh + h;
        float zt[4], rt[4];
        ifft4p(z0[k], z1[k], zt);
        ifft4p(r0[k], r1[k], rt);
        float4 hv = a.hs[idx];
        a.Z[idx] = make_float4(sigm(zt[0] + bz.x), sigm(zt[1] + bz.y),
                               sigm(zt[2] + bz.z), sigm(zt[3] + bz.w));
        float rh0 = sigm(rt[0] + br.x) * hv.x;
        float rh1 = sigm(rt[1] + br.y) * hv.y;
        float rh2 = sigm(rt[2] + br.z) * hv.z;
        float rh3 = sigm(rt[3] + br.w) * hv.w;
        float4 s = fft4(rh0, rh1, rh2, rh3);
        a.RHf[idx] = make_float4(s.x, s.w, s.y, s.z);
        *(ulonglong2*)&a.Gf[idx] = make_ulonglong2(c0[k], c1[k]);
    }
}

struct S2 {
    const float4 *RHf, *Gf, *Z, *hs;
    const float4 *UrP;
    const float2 *UrB;
    const float4 *bias;
    float4 *ht, *hfnew, *out;
};

__global__ void __launch_bounds__(256, 3) k_stage2(S2 A0, S2 A1, int lmask, int t) {
    __shared__ ulonglong2 s_AfP[NT * Nn];
    __shared__ ulonglong2 s_AfB2[Nn * (NT / 2)];
    __shared__ ull s_q0[4 * NT * Hh], s_q1[4 * NT * Hh];
    const int tid = threadIdx.x;
    const int layer = tid >> 7, hid = tid & 127;
    const int bl = hid >> 6, t64 = hid & 63;
    const int b = blockIdx.y * NB + bl;
    const int n0 = blockIdx.x * NT;
    load_tiles(tid, n0, s_AfP, s_AfB2);
    __syncthreads();
    if (!(lmask & (1 << layer))) return;
    const S2 a = layer ? A1 : A0;
    const int qb = (layer * NB + bl) * NT;

    const int c = t64 & 31, half = t64 >> 5;
    {
        ull d0[NT], d1[NT];
        #pragma unroll
        for (int j = 0; j < NT; j++) { d0[j] = 0; d1[j] = 0; }
        const float4* in = a.RHf + (size_t)b * Nn * Hh + c;
        agg_m(in, Hh, half * (Nn / 2), half * (Nn / 2) + Nn / 2, s_AfP, s_AfB2, d0, d1);
        if (half == 0) {
            #pragma unroll
            for (int j = 0; j < NT; j++) {
                s_q0[(qb + j) * Hh + c] = d0[j];
                s_q1[(qb + j) * Hh + c] = d1[j];
            }
        }
        __syncthreads();
        if (half == 1) {
            #pragma unroll
            for (int j = 0; j < NT; j++) {
                int i = (qb + j) * Hh + c;
                s_q0[i] = fadd2(s_q0[i], d0[j]);
                s_q1[i] = fadd2(s_q1[i], d1[j]);
            }
        }
        __syncthreads();
    }

    const int h = t64 & 31, g = t64 >> 5;
    ull t0[3], t1[3];
    #pragma unroll
    for (int k = 0; k < 3; k++) {
        ulonglong2 gv = *(const ulonglong2*)&a.Gf[(b * Nn + n0 + g * 3 + k) * Hh + h];
        t0[k] = gv.x; t1[k] = gv.y;
    }
    const ulonglong2* UrP = (const ulonglong2*)a.UrP;
    for (int j = 0; j < Hh; j++) {
        int wi = j * Hh + h;
        ulonglong2 ur = UrP[wi]; ull urb = f2u(a.UrB[wi].x, a.UrB[wi].y);
        #pragma unroll
        for (int k = 0; k < 3; k++) {
            int i = (qb + g * 3 + k) * Hh + j;
            ull q0 = s_q0[i], q1 = s_q1[i], q2 = swap2(q1);
            ffma2(t0[k], ur.x, q0); ffma2(t1[k], ur.y, q1); ffma2(t1[k], urb, q2);
        }
    }
    const float4 bh = a.bias[2 * Hh + h];
    #pragma unroll
    for (int k = 0; k < 3; k++) {
        int n = n0 + g * 3 + k;
        int idx = (b * Nn + n) * Hh + h;
        float tt[4];
        ifft4p(t0[k], t1[k], tt);
        float4 z = a.Z[idx], hv = a.hs[idx];
        float4 hn;
        hn.x = z.x * hv.x + (1.f - z.x) * tanhf(tt[0] + bh.x);
        hn.y = z.y * hv.y + (1.f - z.y) * tanhf(tt[1] + bh.y);
        hn.z = z.z * hv.z + (1.f - z.z) * tanhf(tt[2] + bh.z);
        hn.w = z.w * hv.w + (1.f - z.w) * tanhf(tt[3] + bh.w);
        a.ht[idx] = hn;
        float4 s = fft4(hn.x, hn.y, hn.z, hn.w);
        a.hfnew[idx] = make_float4(s.x, s.w, s.y, s.z);
        if (a.out) a.out[((b * Tt + t) * Nn + n) * Hh + h] = hn;
    }
}

__global__ void k_hlast(float4* __restrict__ out) {
    int i = blockIdx.x * blockDim.x + threadIdx.x;
    if (i >= 2 * BNH) return;
    out[OUTE / 4 + i] = (i < BNH) ? g_ht[0][1][i] : g_ht[1][1][i - BNH];
}

// ---------------- host ----------------
extern "C" void kernel_launch(void* const* d_in, const int* in_sizes, int n_in,
                              void* d_out, int out_size) {
    const float* inputs = (const float*)d_in[0];
    const float* U      = (const float*)d_in[1];
    const float4* B0p   = (const float4*)d_in[7];
    const float4* B1p   = (const float4*)d_in[13];

    void *pWP, *pWB, *pXf, *phf, *pht, *pz4, *pZ, *pRH, *pG;
    cudaGetSymbolAddress(&pWP, g_WP);
    cudaGetSymbolAddress(&pWB, g_WB);
    cudaGetSymbolAddress(&pXf, g_Xf);
    cudaGetSymbolAddress(&phf, g_hf);
    cudaGetSymbolAddress(&pht, g_ht);
    cudaGetSymbolAddress(&pz4, g_z4);
    cudaGetSymbolAddress(&pZ,  g_Zg);
    cudaGetSymbolAddress(&pRH, g_RH);
    cudaGetSymbolAddress(&pG,  g_Gf);

    auto WPi = [&](int i) { return (const float4*)pWP + (size_t)i * Hh * Hh; };
    auto WBi = [&](int i) { return (const float2*)pWB + (size_t)i * Hh * Hh; };
    float4* Xf = (float4*)pXf;
    float4* hf[2][2]; float4* ht[2][2];
    for (int l = 0; l < 2; l++)
        for (int u = 0; u < 2; u++) {
            hf[l][u] = (float4*)phf + ((size_t)l * 2 + u) * BNH;
            ht[l][u] = (float4*)pht + ((size_t)l * 2 + u) * BNH;
        }
    float4* z4 = (float4*)pz4;
    float4* Zl[2] = {(float4*)pZ, (float4*)pZ + BNH};
    float4* RHl[2] = {(float4*)pRH, (float4*)pRH + BNH};
    float4* Gl[2] = {(float4*)pG, (float4*)pG + BNH};
    float4* out = (float4*)d_out;

    k_adj_raw<<<(Nn * Nn + 127) / 128, 128>>>(U);
    k_softmax<<<dim3(Nn, Rr), 256>>>();
    {
        int tot = XT + BNH + Nn * Nn + 3 * Ff * Hh + 7 * Hh * Hh;
        k_misc<<<(tot + 255) / 256, 256>>>(inputs,
            (const float*)d_in[2], (const float*)d_in[3], (const float*)d_in[4],
            (const float*)d_in[5], (const float*)d_in[6],
            (const float*)d_in[8], (const float*)d_in[9], (const float*)d_in[10],
            (const float*)d_in[11], (const float*)d_in[12]);
    }

    auto mkS1 = [&](int L, int t, int s) -> S1 {
        S1 a;
        if (L == 0) {
            a.Xf = Xf + (size_t)t * Bb * Nn * Ff;
            a.Fin = Ff;
            a.Hf = (t == 0) ? z4 : hf[0][s];
            a.hs = (t == 0) ? z4 : ht[0][s];
            a.WzP = WPi(0); a.WrP = WPi(1); a.WhP = WPi(2); a.UzP = WPi(3); a.UrP = WPi(4);
            a.WzB = WBi(0); a.WrB = WBi(1); a.WhB = WBi(2); a.UzB = WBi(3); a.UrB = WBi(4);
            a.bias = B0p; a.Z = Zl[0]; a.RHf = RHl[0]; a.Gf = Gl[0];
        } else {
            a.Xf = hf[0][s];
            a.Fin = Hh;
            a.Hf = (t == 0) ? z4 : hf[1][s];
            a.hs = (t == 0) ? z4 : ht[1][s];
            a.WzP = WPi(5); a.WrP = WPi(6); a.WhP = WPi(7); a.UzP = WPi(8); a.UrP = WPi(9);
            a.WzB = WBi(5); a.WrB = WBi(6); a.WhB = WBi(7); a.UzB = WBi(8); a.UrB = WBi(9);
            a.bias = B1p; a.Z = Zl[1]; a.RHf = RHl[1]; a.Gf = Gl[1];
        }
        return a;
    };
    auto mkS2 = [&](int L, int t, int s, int d) -> S2 {
        S2 a;
        if (L == 0) {
            a.RHf = RHl[0]; a.Gf = Gl[0]; a.Z = Zl[0];
            a.hs = (t == 0) ? z4 : ht[0][s];
            a.UrP = WPi(4); a.UrB = WBi(4); a.bias = B0p;
            a.ht = ht[0][d]; a.hfnew = hf[0][d]; a.out = nullptr;
        } else {
            a.RHf = RHl[1]; a.Gf = Gl[1]; a.Z = Zl[1];
            a.hs = (t == 0) ? z4 : ht[1][s];
            a.UrP = WPi(9); a.UrB = WBi(9); a.bias = B1p;
            a.ht = ht[1][d]; a.hfnew = hf[1][d]; a.out = out;
        }
        return a;
    };

    const dim3 blk(256);
    const dim3 grd(NTILES, Bb / NB);   // 25 x 16 = 400 blocks, single wave

    // t = 0: layer1 consumes CURRENT layer0 output -> sequential, layer-masked
    { S1 a = mkS1(0, 0, 0);    k_stage1<<<grd, blk>>>(a, a, 1); }
    { S2 a = mkS2(0, 0, 0, 0); k_stage2<<<grd, blk>>>(a, a, 1, 0); }
    { S1 a = mkS1(1, 0, 0);    k_stage1<<<grd, blk>>>(a, a, 2); }
    { S2 a = mkS2(1, 0, 0, 0); k_stage2<<<grd, blk>>>(a, a, 2, 0); }

    // t >= 1: both layers in every block
    for (int t = 1; t < Tt; t++) {
        int s = (t - 1) & 1, d = t & 1;
        S1 a0 = mkS1(0, t, s), a1 = mkS1(1, t, s);
        k_stage1<<<grd, blk>>>(a0, a1, 3);
        S2 c0 = mkS2(0, t, s, d), c1 = mkS2(1, t, s, d);
        k_stage2<<<grd, blk>>>(c0, c1, 3, t);
    }

    k_hlast<<<(2 * BNH + 255) / 256, 256>>>(out);
}